// round 1
// baseline (speedup 1.0000x reference)
#include <cuda_runtime.h>

#define NUM_NODES 100000
#define EMB_DIM   64
#define NUM_EDGES 1280000
#define VEC       (EMB_DIM / 4)   // 16 float4 chunks per node row

// ---- scratch (static device globals; no allocation allowed) ----
__device__ float g_A[NUM_NODES * EMB_DIM];
__device__ float g_B[NUM_NODES * EMB_DIM];
__device__ float g_C[NUM_NODES * EMB_DIM];
__device__ float g_w[NUM_EDGES];
__device__ float g_dinv[NUM_NODES];
__device__ int   g_deg[NUM_NODES];

// Zero the three layer-output buffers and the degree counters.
__global__ void init_kernel() {
    int i = blockIdx.x * blockDim.x + threadIdx.x;
    if (i < NUM_NODES * EMB_DIM) {
        g_A[i] = 0.0f;
        g_B[i] = 0.0f;
        g_C[i] = 0.0f;
    }
    if (i < NUM_NODES) g_deg[i] = 0;
}

// deg[dst] += 1 per edge
__global__ void deg_kernel(const int* __restrict__ dst) {
    int e = blockIdx.x * blockDim.x + threadIdx.x;
    if (e < NUM_EDGES) atomicAdd(&g_deg[dst[e]], 1);
}

// dinv[n] = deg>0 ? rsqrt(deg) : 0
__global__ void dinv_kernel() {
    int n = blockIdx.x * blockDim.x + threadIdx.x;
    if (n < NUM_NODES) {
        int d = g_deg[n];
        g_dinv[n] = (d > 0) ? rsqrtf((float)d) : 0.0f;
    }
}

// w[e] = dinv[src] * dinv[dst]
__global__ void w_kernel(const int* __restrict__ src, const int* __restrict__ dst) {
    int e = blockIdx.x * blockDim.x + threadIdx.x;
    if (e < NUM_EDGES) g_w[e] = g_dinv[src[e]] * g_dinv[dst[e]];
}

// One propagation layer: xnew[dst] += w * x[src].
// 16 threads per edge, one float4 each. layer selects (input, output) buffers:
//   0: emb -> A,  1: A -> B,  2: B -> C
__global__ void scatter_kernel(const int* __restrict__ src,
                               const int* __restrict__ dst,
                               const float4* __restrict__ emb4,
                               int layer) {
    int t = blockIdx.x * blockDim.x + threadIdx.x;
    if (t >= NUM_EDGES * VEC) return;
    int e = t >> 4;     // edge index
    int c = t & 15;     // float4 chunk within the 64-dim row

    const float4* xin;
    float4*       xout;
    if (layer == 0)      { xin = emb4;                    xout = (float4*)g_A; }
    else if (layer == 1) { xin = (const float4*)g_A;      xout = (float4*)g_B; }
    else                 { xin = (const float4*)g_B;      xout = (float4*)g_C; }

    int   s = __ldg(&src[e]);
    int   d = __ldg(&dst[e]);
    float w = __ldg(&g_w[e]);

    float4 v = __ldg(&xin[s * VEC + c]);
    v.x *= w; v.y *= w; v.z *= w; v.w *= w;

    float* p = (float*)(xout + d * VEC + c);
    // sm_90+: vector reduction, no return value (REDG path)
    asm volatile("red.global.add.v4.f32 [%0], {%1, %2, %3, %4};"
                 :: "l"(p), "f"(v.x), "f"(v.y), "f"(v.z), "f"(v.w)
                 : "memory");
}

// out = (emb + A + B + C) / 4, fully streaming float4
__global__ void final_kernel(const float4* __restrict__ emb4, float4* __restrict__ out4) {
    int i = blockIdx.x * blockDim.x + threadIdx.x;
    if (i >= NUM_NODES * VEC) return;
    float4 e = emb4[i];
    const float4 a = ((const float4*)g_A)[i];
    const float4 b = ((const float4*)g_B)[i];
    const float4 c = ((const float4*)g_C)[i];
    float4 r;
    r.x = (e.x + a.x + b.x + c.x) * 0.25f;
    r.y = (e.y + a.y + b.y + c.y) * 0.25f;
    r.z = (e.z + a.z + b.z + c.z) * 0.25f;
    r.w = (e.w + a.w + b.w + c.w) * 0.25f;
    out4[i] = r;
}

extern "C" void kernel_launch(void* const* d_in, const int* in_sizes, int n_in,
                              void* d_out, int out_size) {
    const int*   edge = (const int*)d_in[0];   // [2, NUM_EDGES] row-major
    const float* emb  = (const float*)d_in[1]; // [NUM_NODES, EMB_DIM]
    const int* src = edge;
    const int* dst = edge + NUM_EDGES;
    const float4* emb4 = (const float4*)emb;
    float4* out4 = (float4*)d_out;

    const int TPB = 256;

    // init: zero A/B/C (6.4M floats each) + deg
    init_kernel<<<(NUM_NODES * EMB_DIM + TPB - 1) / TPB, TPB>>>();

    // degree + norm weights
    deg_kernel<<<(NUM_EDGES + TPB - 1) / TPB, TPB>>>(dst);
    dinv_kernel<<<(NUM_NODES + TPB - 1) / TPB, TPB>>>();
    w_kernel<<<(NUM_EDGES + TPB - 1) / TPB, TPB>>>(src, dst);

    // 3 propagation layers
    const int scatter_threads = NUM_EDGES * VEC;       // 20.48M
    const int scatter_blocks  = (scatter_threads + TPB - 1) / TPB;
    scatter_kernel<<<scatter_blocks, TPB>>>(src, dst, emb4, 0);
    scatter_kernel<<<scatter_blocks, TPB>>>(src, dst, emb4, 1);
    scatter_kernel<<<scatter_blocks, TPB>>>(src, dst, emb4, 2);

    // combine
    final_kernel<<<(NUM_NODES * VEC + TPB - 1) / TPB, TPB>>>(emb4, out4);
}

// round 4
// speedup vs baseline: 1.8643x; 1.8643x over previous
#include <cuda_runtime.h>

#define NUM_NODES 100000
#define EMB_DIM   64
#define NUM_EDGES 1280000
#define VEC       (EMB_DIM / 4)   // 16 float4 per node row
#define TILE      1024
#define NUM_TILES ((NUM_NODES + TILE - 1) / TILE)   // 98

// ---- scratch (static device globals; no allocation allowed) ----
__device__ __align__(16) float g_A[NUM_NODES * EMB_DIM];
__device__ __align__(16) float g_B[NUM_NODES * EMB_DIM];
__device__ float g_dinv[NUM_NODES];
__device__ int   g_deg[NUM_NODES];
__device__ int   g_cur[NUM_NODES];          // per-dst fill cursor
__device__ int   g_row[NUM_NODES + 1];      // CSR row offsets
__device__ int   g_tile[NUM_TILES];         // tile totals
__device__ int   g_tpfx[NUM_TILES];         // exclusive tile prefix
__device__ int   g_csrc[NUM_EDGES];         // CSR: src node per slot
__device__ float g_cw[NUM_EDGES];           // CSR: edge weight per slot

// zero counters
__global__ void init_kernel() {
    int i = blockIdx.x * blockDim.x + threadIdx.x;
    if (i < NUM_NODES) { g_deg[i] = 0; g_cur[i] = 0; }
}

// deg[dst] += 1
__global__ void deg_kernel(const int* __restrict__ dst) {
    int e = blockIdx.x * blockDim.x + threadIdx.x;
    if (e < NUM_EDGES) atomicAdd(&g_deg[dst[e]], 1);
}

__global__ void dinv_kernel() {
    int n = blockIdx.x * blockDim.x + threadIdx.x;
    if (n < NUM_NODES) {
        int d = g_deg[n];
        g_dinv[n] = (d > 0) ? rsqrtf((float)d) : 0.0f;
    }
}

// ---- 3-kernel exclusive scan of deg -> g_row ----
__global__ void scan_tiles() {   // per-tile exclusive scan + tile total
    __shared__ int s[TILE];
    int i = blockIdx.x * TILE + threadIdx.x;
    int v = (i < NUM_NODES) ? g_deg[i] : 0;
    s[threadIdx.x] = v;
    __syncthreads();
    #pragma unroll
    for (int off = 1; off < TILE; off <<= 1) {
        int t = (threadIdx.x >= off) ? s[threadIdx.x - off] : 0;
        __syncthreads();
        s[threadIdx.x] += t;
        __syncthreads();
    }
    if (i < NUM_NODES) g_row[i] = s[threadIdx.x] - v;   // exclusive within tile
    if (threadIdx.x == TILE - 1) g_tile[blockIdx.x] = s[TILE - 1];
}

__global__ void scan_tilesums() {   // single block scans NUM_TILES totals
    __shared__ int s[128];
    int t = threadIdx.x;
    int v = (t < NUM_TILES) ? g_tile[t] : 0;
    s[t] = v;
    __syncthreads();
    #pragma unroll
    for (int off = 1; off < 128; off <<= 1) {
        int a = (t >= off) ? s[t - off] : 0;
        __syncthreads();
        s[t] += a;
        __syncthreads();
    }
    if (t < NUM_TILES) g_tpfx[t] = s[t] - v;   // exclusive
}

__global__ void scan_apply() {
    int i = blockIdx.x * blockDim.x + threadIdx.x;
    if (i < NUM_NODES) g_row[i] += g_tpfx[i / TILE];
    if (i == 0) g_row[NUM_NODES] = NUM_EDGES;
}

// bucket edges by dst; compute weight inline
__global__ void fill_kernel(const int* __restrict__ src, const int* __restrict__ dst) {
    int e = blockIdx.x * blockDim.x + threadIdx.x;
    if (e >= NUM_EDGES) return;
    int s = src[e];
    int d = dst[e];
    int pos = g_row[d] + atomicAdd(&g_cur[d], 1);
    g_csrc[pos] = s;
    g_cw[pos]   = g_dinv[s] * g_dinv[d];
}

// Pull-mode propagation: xout[d] = sum_e w_e * xin[src_e].
// 16 threads per dst node, one float4 lane each. No atomics, one clean write.
// Buffer selection happens IN DEVICE CODE via `layer`:
//   layer 0: emb -> A
//   layer 1: A   -> B
//   layer 2: B   -> (fused) out = (emb + A + B + conv(B)) / 4
__global__ void pull_kernel(const float4* __restrict__ emb4,
                            float4* __restrict__ out4,
                            int layer) {
    int g = blockIdx.x * (blockDim.x >> 4) + (threadIdx.x >> 4);  // dst node
    int c = threadIdx.x & 15;                                     // float4 lane
    if (g >= NUM_NODES) return;

    const float4* xin;
    if (layer == 0)      xin = emb4;
    else if (layer == 1) xin = (const float4*)g_A;
    else                 xin = (const float4*)g_B;

    int beg = g_row[g];
    int end = g_row[g + 1];

    float4 acc = make_float4(0.f, 0.f, 0.f, 0.f);
    int e = beg;
    for (; e + 2 <= end; e += 2) {        // 2-way unroll for MLP vs L2 latency
        int   s0 = __ldg(&g_csrc[e]);
        int   s1 = __ldg(&g_csrc[e + 1]);
        float w0 = __ldg(&g_cw[e]);
        float w1 = __ldg(&g_cw[e + 1]);
        float4 v0 = __ldg(&xin[s0 * VEC + c]);
        float4 v1 = __ldg(&xin[s1 * VEC + c]);
        acc.x += w0 * v0.x + w1 * v1.x;
        acc.y += w0 * v0.y + w1 * v1.y;
        acc.z += w0 * v0.z + w1 * v1.z;
        acc.w += w0 * v0.w + w1 * v1.w;
    }
    if (e < end) {
        int   s0 = __ldg(&g_csrc[e]);
        float w0 = __ldg(&g_cw[e]);
        float4 v0 = __ldg(&xin[s0 * VEC + c]);
        acc.x += w0 * v0.x;
        acc.y += w0 * v0.y;
        acc.z += w0 * v0.z;
        acc.w += w0 * v0.w;
    }

    int idx = g * VEC + c;
    if (layer == 0) {
        ((float4*)g_A)[idx] = acc;
    } else if (layer == 1) {
        ((float4*)g_B)[idx] = acc;
    } else {
        float4 em = __ldg(&emb4[idx]);
        float4 a  = ((const float4*)g_A)[idx];
        float4 b  = ((const float4*)g_B)[idx];
        float4 r;
        r.x = (em.x + a.x + b.x + acc.x) * 0.25f;
        r.y = (em.y + a.y + b.y + acc.y) * 0.25f;
        r.z = (em.z + a.z + b.z + acc.z) * 0.25f;
        r.w = (em.w + a.w + b.w + acc.w) * 0.25f;
        out4[idx] = r;
    }
}

extern "C" void kernel_launch(void* const* d_in, const int* in_sizes, int n_in,
                              void* d_out, int out_size) {
    const int*   edge = (const int*)d_in[0];   // [2, NUM_EDGES]
    const float* emb  = (const float*)d_in[1]; // [NUM_NODES, EMB_DIM]
    const int* src = edge;
    const int* dst = edge + NUM_EDGES;
    const float4* emb4 = (const float4*)emb;
    float4* out4 = (float4*)d_out;

    const int TPB = 256;

    init_kernel<<<(NUM_NODES + TPB - 1) / TPB, TPB>>>();
    deg_kernel<<<(NUM_EDGES + TPB - 1) / TPB, TPB>>>(dst);
    dinv_kernel<<<(NUM_NODES + TPB - 1) / TPB, TPB>>>();

    scan_tiles<<<NUM_TILES, TILE>>>();
    scan_tilesums<<<1, 128>>>();
    scan_apply<<<(NUM_NODES + TPB - 1) / TPB, TPB>>>();

    fill_kernel<<<(NUM_EDGES + TPB - 1) / TPB, TPB>>>(src, dst);

    const int nodes_per_block = TPB / 16;
    const int pull_blocks = (NUM_NODES + nodes_per_block - 1) / nodes_per_block;

    pull_kernel<<<pull_blocks, TPB>>>(emb4, out4, 0);  // emb -> A
    pull_kernel<<<pull_blocks, TPB>>>(emb4, out4, 1);  // A   -> B
    pull_kernel<<<pull_blocks, TPB>>>(emb4, out4, 2);  // B -> out (fused combine)
}

// round 5
// speedup vs baseline: 2.4002x; 1.2875x over previous
#include <cuda_runtime.h>
#include <cuda_fp16.h>

#define NUM_NODES 100000
#define EMB_DIM   64
#define NUM_EDGES 1280000
#define TILE      1024
#define NUM_TILES ((NUM_NODES + TILE - 1) / TILE)   // 98

// ---- scratch (static device globals; no allocation allowed) ----
__device__ __align__(16) __half g_E16[NUM_NODES * EMB_DIM];  // emb in fp16
__device__ __align__(16) __half g_A16[NUM_NODES * EMB_DIM];  // layer-1 out
__device__ __align__(16) __half g_B16[NUM_NODES * EMB_DIM];  // layer-2 out
__device__ float g_dinv[NUM_NODES];
__device__ int   g_deg[NUM_NODES];
__device__ int   g_row[NUM_NODES];          // CSR offsets (bumped by fill)
__device__ int   g_tile[NUM_TILES];
__device__ int   g_tpfx[NUM_TILES];
__device__ __align__(16) int2 g_meta[NUM_EDGES];   // (src, w-as-int) per slot

__global__ void init_kernel() {
    int i = blockIdx.x * blockDim.x + threadIdx.x;
    if (i < NUM_NODES) g_deg[i] = 0;
}

__global__ void deg_kernel(const int* __restrict__ dst) {
    int e = blockIdx.x * blockDim.x + threadIdx.x;
    if (e < NUM_EDGES) atomicAdd(&g_deg[dst[e]], 1);
}

// emb fp32 -> fp16 (each thread: one float4 -> 4 halves)
__global__ void convert_kernel(const float4* __restrict__ emb4) {
    int i = blockIdx.x * blockDim.x + threadIdx.x;
    if (i >= NUM_NODES * EMB_DIM / 4) return;
    float4 v = __ldg(&emb4[i]);
    __half2 lo = __floats2half2_rn(v.x, v.y);
    __half2 hi = __floats2half2_rn(v.z, v.w);
    uint2 p;
    p.x = *reinterpret_cast<unsigned*>(&lo);
    p.y = *reinterpret_cast<unsigned*>(&hi);
    reinterpret_cast<uint2*>(g_E16)[i] = p;
}

// per-tile exclusive scan of deg -> g_row; also emit dinv (deg already loaded)
__global__ void scan_tiles() {
    __shared__ int s[TILE];
    int i = blockIdx.x * TILE + threadIdx.x;
    int v = (i < NUM_NODES) ? g_deg[i] : 0;
    if (i < NUM_NODES) g_dinv[i] = (v > 0) ? rsqrtf((float)v) : 0.0f;
    s[threadIdx.x] = v;
    __syncthreads();
    #pragma unroll
    for (int off = 1; off < TILE; off <<= 1) {
        int t = (threadIdx.x >= off) ? s[threadIdx.x - off] : 0;
        __syncthreads();
        s[threadIdx.x] += t;
        __syncthreads();
    }
    if (i < NUM_NODES) g_row[i] = s[threadIdx.x] - v;   // exclusive within tile
    if (threadIdx.x == TILE - 1) g_tile[blockIdx.x] = s[TILE - 1];
}

__global__ void scan_tilesums() {
    __shared__ int s[128];
    int t = threadIdx.x;
    int v = (t < NUM_TILES) ? g_tile[t] : 0;
    s[t] = v;
    __syncthreads();
    #pragma unroll
    for (int off = 1; off < 128; off <<= 1) {
        int a = (t >= off) ? s[t - off] : 0;
        __syncthreads();
        s[t] += a;
        __syncthreads();
    }
    if (t < NUM_TILES) g_tpfx[t] = s[t] - v;
}

__global__ void scan_apply() {
    int i = blockIdx.x * blockDim.x + threadIdx.x;
    if (i < NUM_NODES) g_row[i] += g_tpfx[i / TILE];
}

// bucket edges by dst, bumping g_row in place.
// After this: g_row[d] == original row[d+1]; pull uses beg=row[g-1], end=row[g].
__global__ void fill_kernel(const int* __restrict__ src, const int* __restrict__ dst) {
    int e = blockIdx.x * blockDim.x + threadIdx.x;
    if (e >= NUM_EDGES) return;
    int s = src[e];
    int d = dst[e];
    int pos = atomicAdd(&g_row[d], 1);
    g_meta[pos] = make_int2(s, __float_as_int(g_dinv[s] * g_dinv[d]));
}

__device__ __forceinline__ float2 h2f(unsigned u) {
    __half2 h = *reinterpret_cast<__half2*>(&u);
    return __half22float2(h);
}

// Pull-mode propagation, fp16 rows. 8 threads per dst node, 16B (8 halves) each.
//   layer 0: E16 -> A16,  layer 1: A16 -> B16,
//   layer 2: B16 -> fused out = (emb + A + B + acc) * 0.25 (fp32)
__global__ void pull_kernel(const float4* __restrict__ emb4,
                            float4* __restrict__ out4,
                            int layer) {
    int g = blockIdx.x * (blockDim.x >> 3) + (threadIdx.x >> 3);  // dst node
    int c = threadIdx.x & 7;                                      // 16B lane
    if (g >= NUM_NODES) return;

    const uint4* xin;
    if (layer == 0)      xin = (const uint4*)g_E16;
    else if (layer == 1) xin = (const uint4*)g_A16;
    else                 xin = (const uint4*)g_B16;

    int beg = (g == 0) ? 0 : __ldg(&g_row[g - 1]);
    int end = __ldg(&g_row[g]);

    float acc[8] = {0.f, 0.f, 0.f, 0.f, 0.f, 0.f, 0.f, 0.f};

    int e = beg;
    for (; e + 2 <= end; e += 2) {
        int2 m0 = __ldg(&g_meta[e]);
        int2 m1 = __ldg(&g_meta[e + 1]);
        float w0 = __int_as_float(m0.y);
        float w1 = __int_as_float(m1.y);
        uint4 v0 = __ldg(&xin[m0.x * 8 + c]);
        uint4 v1 = __ldg(&xin[m1.x * 8 + c]);
        float2 f;
        f = h2f(v0.x); acc[0] += w0 * f.x; acc[1] += w0 * f.y;
        f = h2f(v0.y); acc[2] += w0 * f.x; acc[3] += w0 * f.y;
        f = h2f(v0.z); acc[4] += w0 * f.x; acc[5] += w0 * f.y;
        f = h2f(v0.w); acc[6] += w0 * f.x; acc[7] += w0 * f.y;
        f = h2f(v1.x); acc[0] += w1 * f.x; acc[1] += w1 * f.y;
        f = h2f(v1.y); acc[2] += w1 * f.x; acc[3] += w1 * f.y;
        f = h2f(v1.z); acc[4] += w1 * f.x; acc[5] += w1 * f.y;
        f = h2f(v1.w); acc[6] += w1 * f.x; acc[7] += w1 * f.y;
    }
    if (e < end) {
        int2 m0 = __ldg(&g_meta[e]);
        float w0 = __int_as_float(m0.y);
        uint4 v0 = __ldg(&xin[m0.x * 8 + c]);
        float2 f;
        f = h2f(v0.x); acc[0] += w0 * f.x; acc[1] += w0 * f.y;
        f = h2f(v0.y); acc[2] += w0 * f.x; acc[3] += w0 * f.y;
        f = h2f(v0.z); acc[4] += w0 * f.x; acc[5] += w0 * f.y;
        f = h2f(v0.w); acc[6] += w0 * f.x; acc[7] += w0 * f.y;
    }

    if (layer < 2) {
        __half2 h0 = __floats2half2_rn(acc[0], acc[1]);
        __half2 h1 = __floats2half2_rn(acc[2], acc[3]);
        __half2 h2 = __floats2half2_rn(acc[4], acc[5]);
        __half2 h3 = __floats2half2_rn(acc[6], acc[7]);
        uint4 p;
        p.x = *reinterpret_cast<unsigned*>(&h0);
        p.y = *reinterpret_cast<unsigned*>(&h1);
        p.z = *reinterpret_cast<unsigned*>(&h2);
        p.w = *reinterpret_cast<unsigned*>(&h3);
        uint4* xout = (layer == 0) ? (uint4*)g_A16 : (uint4*)g_B16;
        xout[g * 8 + c] = p;
    } else {
        // fused final combine: out = (emb + A + B + acc) / 4, fp32
        uint4 ap = ((const uint4*)g_A16)[g * 8 + c];
        uint4 bp = ((const uint4*)g_B16)[g * 8 + c];
        float2 a0 = h2f(ap.x), a1 = h2f(ap.y), a2 = h2f(ap.z), a3 = h2f(ap.w);
        float2 b0 = h2f(bp.x), b1 = h2f(bp.y), b2 = h2f(bp.z), b3 = h2f(bp.w);
        int base = g * 16 + c * 2;            // float4 index into emb/out
        float4 e0 = __ldg(&emb4[base]);
        float4 e1 = __ldg(&emb4[base + 1]);
        float4 r0, r1;
        r0.x = (e0.x + a0.x + b0.x + acc[0]) * 0.25f;
        r0.y = (e0.y + a0.y + b0.y + acc[1]) * 0.25f;
        r0.z = (e0.z + a1.x + b1.x + acc[2]) * 0.25f;
        r0.w = (e0.w + a1.y + b1.y + acc[3]) * 0.25f;
        r1.x = (e1.x + a2.x + b2.x + acc[4]) * 0.25f;
        r1.y = (e1.y + a2.y + b2.y + acc[5]) * 0.25f;
        r1.z = (e1.z + a3.x + b3.x + acc[6]) * 0.25f;
        r1.w = (e1.w + a3.y + b3.y + acc[7]) * 0.25f;
        out4[base]     = r0;
        out4[base + 1] = r1;
    }
}

extern "C" void kernel_launch(void* const* d_in, const int* in_sizes, int n_in,
                              void* d_out, int out_size) {
    const int*   edge = (const int*)d_in[0];   // [2, NUM_EDGES]
    const float* emb  = (const float*)d_in[1]; // [NUM_NODES, EMB_DIM]
    const int* src = edge;
    const int* dst = edge + NUM_EDGES;
    const float4* emb4 = (const float4*)emb;
    float4* out4 = (float4*)d_out;

    const int TPB = 256;

    init_kernel<<<(NUM_NODES + TPB - 1) / TPB, TPB>>>();
    deg_kernel<<<(NUM_EDGES + TPB - 1) / TPB, TPB>>>(dst);
    convert_kernel<<<(NUM_NODES * EMB_DIM / 4 + TPB - 1) / TPB, TPB>>>(emb4);

    scan_tiles<<<NUM_TILES, TILE>>>();
    scan_tilesums<<<1, 128>>>();
    scan_apply<<<(NUM_NODES + TPB - 1) / TPB, TPB>>>();

    fill_kernel<<<(NUM_EDGES + TPB - 1) / TPB, TPB>>>(src, dst);

    const int nodes_per_block = TPB / 8;   // 32
    const int pull_blocks = (NUM_NODES + nodes_per_block - 1) / nodes_per_block;

    pull_kernel<<<pull_blocks, TPB>>>(emb4, out4, 0);  // E16 -> A16
    pull_kernel<<<pull_blocks, TPB>>>(emb4, out4, 1);  // A16 -> B16
    pull_kernel<<<pull_blocks, TPB>>>(emb4, out4, 2);  // B16 -> out (fused)
}